// round 13
// baseline (speedup 1.0000x reference)
#include <cuda_runtime.h>
#include <cuda_fp16.h>
#include <cstdint>

#define DIN   4096
#define DOUT  4096
#define MROWS 8192
#define RANK  16

#define BM 128
#define BN 256
#define BK 64
#define STAGES 3
#define NCHUNK (DIN / BK)            // 64
#define NTHREADS 512

// 144-byte row stride: conflict-free ldmatrix & cp.async.
#define ROWB 144
#define A_BYTES (BM * ROWB)          // 18432
#define B_BYTES (BN * ROWB)          // 36864
#define STAGE_BYTES (A_BYTES + B_BYTES)  // 55296
#define SMEM_DYN (STAGES * STAGE_BYTES + 2048)  // 167936

__device__ __half g_Xh[(size_t)MROWS * DIN];   // 64 MB
__device__ __half g_Wh[(size_t)DOUT * DIN];    // 32 MB  W_eff[n][k]

// ---------------------------------------------------------------------------
// Fused prep: W blocks first (longer), then streaming x conversion.
// ---------------------------------------------------------------------------
#define W_BLOCKS 4096
#define X_BLOCKS ((MROWS * DIN) / (256 * 8))   // 16384

__global__ __launch_bounds__(256)
void prep_kernel(const int*   __restrict__ qw,
                 const float* __restrict__ scales,
                 const float* __restrict__ lA,   // [DIN][RANK]
                 const float* __restrict__ lB,   // [RANK][DOUT]
                 const float* __restrict__ x) {
    __shared__ __align__(16) float sB[64 * 20];
    const int bid = blockIdx.x;
    const int tid = threadIdx.x;

    if (bid < W_BLOCKS) {
        const int lane = tid & 31;
        const int w    = tid >> 5;
        const int k0   = (bid & 63) * 64 + lane * 2;
        const int nb0  = (bid >> 6) * 64;

#pragma unroll
        for (int j = 0; j < 4; j++) {
            int idx = tid + j * 256;
            int r = idx >> 6, n = idx & 63;
            sB[n * 20 + r] = lB[(size_t)r * DOUT + nb0 + n];
        }

        float a[32];
        const float4* pa = reinterpret_cast<const float4*>(&lA[(size_t)k0 * RANK]);
#pragma unroll
        for (int q = 0; q < 8; q++)
            reinterpret_cast<float4*>(a)[q] = pa[q];

        __syncthreads();

        const float s = scales[0];
#pragma unroll
        for (int j = 0; j < 8; j++) {
            const int nl = w * 8 + j;
            const int n  = nb0 + nl;
            int2 q2 = *reinterpret_cast<const int2*>(&qw[(size_t)n * DIN + k0]);
            float acc0 = (float)q2.x * s;
            float acc1 = (float)q2.y * s;
            float bq[16];
#pragma unroll
            for (int q = 0; q < 4; q++)
                reinterpret_cast<float4*>(bq)[q] =
                    *reinterpret_cast<const float4*>(&sB[nl * 20 + q * 4]);
#pragma unroll
            for (int r = 0; r < RANK; r++) {
                acc0 += a[r]      * bq[r];
                acc1 += a[16 + r] * bq[r];
            }
            *reinterpret_cast<__half2*>(&g_Wh[(size_t)n * DIN + k0]) =
                __floats2half2_rn(acc0, acc1);
        }
    } else {
        size_t base = ((size_t)(bid - W_BLOCKS) * 256 + tid) * 8;
        float4 v0 = *reinterpret_cast<const float4*>(x + base);
        float4 v1 = *reinterpret_cast<const float4*>(x + base + 4);
        __half2 h[4];
        h[0] = __floats2half2_rn(v0.x, v0.y);
        h[1] = __floats2half2_rn(v0.z, v0.w);
        h[2] = __floats2half2_rn(v1.x, v1.y);
        h[3] = __floats2half2_rn(v1.z, v1.w);
        *reinterpret_cast<uint4*>(&g_Xh[base]) = *reinterpret_cast<uint4*>(h);
    }
}

// ---------------------------------------------------------------------------
__device__ __forceinline__ uint32_t smem_u32(const void* p) {
    uint32_t a;
    asm("{ .reg .u64 t; cvta.to.shared.u64 t, %1; cvt.u32.u64 %0, t; }" : "=r"(a) : "l"(p));
    return a;
}
__device__ __forceinline__ void cp16(uint32_t dst, const void* src) {
    asm volatile("cp.async.cg.shared.global [%0], [%1], 16;" :: "r"(dst), "l"(src));
}
__device__ __forceinline__ void ldsm4(uint32_t& r0, uint32_t& r1, uint32_t& r2,
                                      uint32_t& r3, uint32_t addr) {
    asm volatile("ldmatrix.sync.aligned.m8n8.x4.shared.b16 {%0,%1,%2,%3}, [%4];"
                 : "=r"(r0), "=r"(r1), "=r"(r2), "=r"(r3) : "r"(addr));
}
__device__ __forceinline__ void mma16816(float* c, const uint32_t* a,
                                         const uint32_t* b) {
    asm volatile(
        "mma.sync.aligned.m16n8k16.row.col.f32.f16.f16.f32 "
        "{%0,%1,%2,%3}, {%4,%5,%6,%7}, {%8,%9}, {%0,%1,%2,%3};\n"
        : "+f"(c[0]), "+f"(c[1]), "+f"(c[2]), "+f"(c[3])
        : "r"(a[0]), "r"(a[1]), "r"(a[2]), "r"(a[3]), "r"(b[0]), "r"(b[1]));
}

// ---------------------------------------------------------------------------
// GEMM: CTA 128x256, 16 warps (4x4), warp tile 32x64, BK=64, 3-stage cp.async.
// 4 warps/SMSP hide each other's LDSM latency and barrier phases; fragments
// single-buffered to stay under the 128-reg cap at 512 threads.
// ---------------------------------------------------------------------------
__global__ __launch_bounds__(NTHREADS, 1)
void qlora_hmma_kernel(const float* __restrict__ bias,
                       float*       __restrict__ out) {
    extern __shared__ char smem_raw[];
    uint32_t sbase = smem_u32(smem_raw);
    float* sbias = (float*)(smem_raw + STAGES * STAGE_BYTES);

    const int tid  = threadIdx.x;
    const int warp = tid >> 5;
    const int lane = tid & 31;
    const int bm = blockIdx.y * BM;
    const int bn = blockIdx.x * BN;
    const int wm = (warp >> 2) * 32;       // 0,32,64,96
    const int wn = (warp & 3) * 64;        // 0..192

    if (tid < 256) sbias[tid] = bias[bn + tid];

    const uint32_t a_loff = (uint32_t)((lane & 15) * ROWB + (lane >> 4) * 16)
                            + (uint32_t)wm * ROWB;
    const uint32_t b_loff = (uint32_t)((((lane >> 4) << 3) + (lane & 7)) * ROWB
                                       + ((lane >> 3) & 1) * 16)
                            + (uint32_t)wn * ROWB + A_BYTES;

    float c[2][8][4];
#pragma unroll
    for (int i = 0; i < 2; i++)
#pragma unroll
        for (int j = 0; j < 8; j++)
#pragma unroll
            for (int q = 0; q < 4; q++) c[i][j][q] = 0.f;

    auto load_chunk = [&](int chunk, int slot) {
        const int k0 = chunk * BK;
        uint32_t abase = sbase + slot * STAGE_BYTES;
        uint32_t bbase = abase + A_BYTES;
#pragma unroll
        for (int j = 0; j < 2; j++) {               // A: 1024 x 16B / 512 thr
            int id = tid + j * NTHREADS;
            int row = id >> 3, cc = id & 7;
            cp16(abase + row * ROWB + cc * 16,
                 &g_Xh[(size_t)(bm + row) * DIN + k0 + cc * 8]);
        }
#pragma unroll
        for (int j = 0; j < 4; j++) {               // B: 2048 x 16B / 512 thr
            int id = tid + j * NTHREADS;
            int row = id >> 3, cc = id & 7;
            cp16(bbase + row * ROWB + cc * 16,
                 &g_Wh[(size_t)(bn + row) * DIN + k0 + cc * 8]);
        }
    };

    // ---- prologue ----
#pragma unroll
    for (int s = 0; s < STAGES; s++) {
        load_chunk(s, s);
        asm volatile("cp.async.commit_group;" ::: "memory");
    }
    asm volatile("cp.async.wait_group 2;" ::: "memory");
    __syncthreads();

    // ---- mainloop: 64 iterations, one barrier each ----
    int slot_cur = 0, slot_nxt = 1;
    for (int i = 0; i < NCHUNK; i++) {
        uint32_t ab = sbase + (uint32_t)slot_cur * STAGE_BYTES + a_loff;
        uint32_t bb = sbase + (uint32_t)slot_cur * STAGE_BYTES + b_loff;
#pragma unroll
        for (int s = 0; s < 4; s++) {               // four k16 steps
            uint32_t a[2][4], b[4][4];
#pragma unroll
            for (int mt = 0; mt < 2; mt++)
                ldsm4(a[mt][0], a[mt][1], a[mt][2], a[mt][3],
                      ab + (uint32_t)(mt * 16 * ROWB + s * 32));
#pragma unroll
            for (int g = 0; g < 4; g++)
                ldsm4(b[g][0], b[g][1], b[g][2], b[g][3],
                      bb + (uint32_t)(g * 16 * ROWB + s * 32));
#pragma unroll
            for (int mt = 0; mt < 2; mt++)
#pragma unroll
                for (int g = 0; g < 4; g++) {
                    mma16816(c[mt][2 * g],     a[mt], &b[g][0]);
                    mma16816(c[mt][2 * g + 1], a[mt], &b[g][2]);
                }
        }

        asm volatile("cp.async.wait_group 1;" ::: "memory");
        __syncthreads();

        if (i + STAGES < NCHUNK)
            load_chunk(i + STAGES, slot_cur);       // slot(i+3) == slot(i)
        asm volatile("cp.async.commit_group;" ::: "memory");

        slot_cur = slot_nxt;
        slot_nxt = (slot_nxt == STAGES - 1) ? 0 : slot_nxt + 1;
    }

    // ---- epilogue: + bias, fp32 stores ----
    const int qrow = lane >> 2;
    const int qcol = (lane & 3) * 2;
#pragma unroll
    for (int mt = 0; mt < 2; mt++) {
        int r0 = bm + wm + mt * 16 + qrow;
#pragma unroll
        for (int g = 0; g < 4; g++) {
#pragma unroll
            for (int h = 0; h < 2; h++) {
                int col = bn + wn + g * 16 + h * 8 + qcol;
                float bb0 = sbias[col - bn];
                float bb1 = sbias[col - bn + 1];
                float* cc = c[mt][2 * g + h];
                *reinterpret_cast<float2*>(&out[(size_t)r0 * DOUT + col]) =
                    make_float2(cc[0] + bb0, cc[1] + bb1);
                *reinterpret_cast<float2*>(&out[(size_t)(r0 + 8) * DOUT + col]) =
                    make_float2(cc[2] + bb0, cc[3] + bb1);
            }
        }
    }
}

// ---------------------------------------------------------------------------
extern "C" void kernel_launch(void* const* d_in, const int* in_sizes, int n_in,
                              void* d_out, int out_size) {
    const float* x      = (const float*)d_in[0];
    const int*   qw     = (const int*)  d_in[1];
    const float* scales = (const float*)d_in[2];
    const float* bias   = (const float*)d_in[3];
    const float* lA     = (const float*)d_in[4];
    const float* lB     = (const float*)d_in[5];
    float*       out    = (float*)d_out;

    prep_kernel<<<W_BLOCKS + X_BLOCKS, 256>>>(qw, scales, lA, lB, x);
    {
        cudaFuncSetAttribute(qlora_hmma_kernel,
                             cudaFuncAttributeMaxDynamicSharedMemorySize, SMEM_DYN);
        dim3 grid(DOUT / BN, MROWS / BM);
        qlora_hmma_kernel<<<grid, NTHREADS, SMEM_DYN>>>(bias, out);
    }
}

// round 15
// speedup vs baseline: 1.2572x; 1.2572x over previous
#include <cuda_runtime.h>
#include <cuda_fp16.h>
#include <cstdint>

#define DIN   4096
#define DOUT  4096
#define MROWS 8192
#define RANK  16

#define BM 128
#define BN 256
#define BK 64
#define STAGES 3
#define NCHUNK (DIN / BK)            // 64

// 144-byte row stride: conflict-free ldmatrix & cp.async.
#define ROWB 144
#define A_BYTES (BM * ROWB)          // 18432
#define B_BYTES (BN * ROWB)          // 36864
#define STAGE_BYTES (A_BYTES + B_BYTES)  // 55296
#define SMEM_DYN (STAGES * STAGE_BYTES + 2048)  // 167936

__device__ __half g_Xh[(size_t)MROWS * DIN];   // 64 MB
__device__ __half g_Wh[(size_t)DOUT * DIN];    // 32 MB  W_eff[n][k]

// ---------------------------------------------------------------------------
// Fused prep. W branch: all 8 qw loads hoisted (MLP=8) before the FMA chain.
// ---------------------------------------------------------------------------
#define W_BLOCKS 4096
#define X_BLOCKS ((MROWS * DIN) / (256 * 8))   // 16384

__global__ __launch_bounds__(256)
void prep_kernel(const int*   __restrict__ qw,
                 const float* __restrict__ scales,
                 const float* __restrict__ lA,   // [DIN][RANK]
                 const float* __restrict__ lB,   // [RANK][DOUT]
                 const float* __restrict__ x) {
    __shared__ __align__(16) float sB[64 * 20];
    const int bid = blockIdx.x;
    const int tid = threadIdx.x;

    if (bid < W_BLOCKS) {
        const int lane = tid & 31;
        const int w    = tid >> 5;
        const int k0   = (bid & 63) * 64 + lane * 2;
        const int nb0  = (bid >> 6) * 64;

#pragma unroll
        for (int j = 0; j < 4; j++) {
            int idx = tid + j * 256;
            int r = idx >> 6, n = idx & 63;
            sB[n * 20 + r] = lB[(size_t)r * DOUT + nb0 + n];
        }

        // hoist all 8 qw loads: 8 independent LDG in flight (MLP=8)
        int2 q2a[8];
#pragma unroll
        for (int j = 0; j < 8; j++)
            q2a[j] = *reinterpret_cast<const int2*>(
                &qw[(size_t)(nb0 + w * 8 + j) * DIN + k0]);

        float a[32];
        const float4* pa = reinterpret_cast<const float4*>(&lA[(size_t)k0 * RANK]);
#pragma unroll
        for (int q = 0; q < 8; q++)
            reinterpret_cast<float4*>(a)[q] = pa[q];

        __syncthreads();

        const float s = scales[0];
#pragma unroll
        for (int j = 0; j < 8; j++) {
            const int nl = w * 8 + j;
            const int n  = nb0 + nl;
            float acc0 = (float)q2a[j].x * s;
            float acc1 = (float)q2a[j].y * s;
            float bq[16];
#pragma unroll
            for (int q = 0; q < 4; q++)
                reinterpret_cast<float4*>(bq)[q] =
                    *reinterpret_cast<const float4*>(&sB[nl * 20 + q * 4]);
#pragma unroll
            for (int r = 0; r < RANK; r++) {
                acc0 += a[r]      * bq[r];
                acc1 += a[16 + r] * bq[r];
            }
            *reinterpret_cast<__half2*>(&g_Wh[(size_t)n * DIN + k0]) =
                __floats2half2_rn(acc0, acc1);
        }
    } else {
        size_t base = ((size_t)(bid - W_BLOCKS) * 256 + tid) * 8;
        float4 v0 = *reinterpret_cast<const float4*>(x + base);
        float4 v1 = *reinterpret_cast<const float4*>(x + base + 4);
        __half2 h[4];
        h[0] = __floats2half2_rn(v0.x, v0.y);
        h[1] = __floats2half2_rn(v0.z, v0.w);
        h[2] = __floats2half2_rn(v1.x, v1.y);
        h[3] = __floats2half2_rn(v1.z, v1.w);
        *reinterpret_cast<uint4*>(&g_Xh[base]) = *reinterpret_cast<uint4*>(h);
    }
}

// ---------------------------------------------------------------------------
__device__ __forceinline__ uint32_t smem_u32(const void* p) {
    uint32_t a;
    asm("{ .reg .u64 t; cvta.to.shared.u64 t, %1; cvt.u32.u64 %0, t; }" : "=r"(a) : "l"(p));
    return a;
}
__device__ __forceinline__ void cp16(uint32_t dst, const void* src) {
    asm volatile("cp.async.cg.shared.global [%0], [%1], 16;" :: "r"(dst), "l"(src));
}
__device__ __forceinline__ void ldsm4(uint32_t& r0, uint32_t& r1, uint32_t& r2,
                                      uint32_t& r3, uint32_t addr) {
    asm volatile("ldmatrix.sync.aligned.m8n8.x4.shared.b16 {%0,%1,%2,%3}, [%4];"
                 : "=r"(r0), "=r"(r1), "=r"(r2), "=r"(r3) : "r"(addr));
}
__device__ __forceinline__ void mma16816(float* c, const uint32_t* a,
                                         const uint32_t* b) {
    asm volatile(
        "mma.sync.aligned.m16n8k16.row.col.f32.f16.f16.f32 "
        "{%0,%1,%2,%3}, {%4,%5,%6,%7}, {%8,%9}, {%0,%1,%2,%3};\n"
        : "+f"(c[0]), "+f"(c[1]), "+f"(c[2]), "+f"(c[3])
        : "r"(a[0]), "r"(a[1]), "r"(a[2]), "r"(a[3]), "r"(b[0]), "r"(b[1]));
}

// ---------------------------------------------------------------------------
// GEMM (round-12 winner, verbatim): CTA 128x256, 8 warps, warp tile 64x64,
// BK=64 chunks, 3-stage cp.async, register double-buffered fragments.
// ---------------------------------------------------------------------------
__global__ __launch_bounds__(256)
void qlora_hmma_kernel(const float* __restrict__ bias,
                       float*       __restrict__ out) {
    extern __shared__ char smem_raw[];
    uint32_t sbase = smem_u32(smem_raw);
    float* sbias = (float*)(smem_raw + STAGES * STAGE_BYTES);

    const int tid  = threadIdx.x;
    const int warp = tid >> 5;
    const int lane = tid & 31;
    const int bm = blockIdx.y * BM;
    const int bn = blockIdx.x * BN;
    const int wm = (warp >> 2) * 64;
    const int wn = (warp & 3) * 64;

    sbias[tid] = bias[bn + tid];

    const uint32_t a_loff = (uint32_t)((lane & 15) * ROWB + (lane >> 4) * 16)
                            + (uint32_t)wm * ROWB;
    const uint32_t b_loff = (uint32_t)((((lane >> 4) << 3) + (lane & 7)) * ROWB
                                       + ((lane >> 3) & 1) * 16)
                            + (uint32_t)wn * ROWB + A_BYTES;

    float c[4][8][4];
#pragma unroll
    for (int i = 0; i < 4; i++)
#pragma unroll
        for (int j = 0; j < 8; j++)
#pragma unroll
            for (int q = 0; q < 4; q++) c[i][j][q] = 0.f;

    uint32_t a0[4][4], b0[4][4], a1[4][4], b1[4][4];

    auto load_chunk = [&](int chunk, int slot) {
        const int k0 = chunk * BK;
        uint32_t abase = sbase + slot * STAGE_BYTES;
        uint32_t bbase = abase + A_BYTES;
#pragma unroll
        for (int j = 0; j < 4; j++) {               // A: 1024 x 16B
            int id = tid + j * 256;
            int row = id >> 3, cc = id & 7;
            cp16(abase + row * ROWB + cc * 16,
                 &g_Xh[(size_t)(bm + row) * DIN + k0 + cc * 8]);
        }
#pragma unroll
        for (int j = 0; j < 8; j++) {               // B: 2048 x 16B
            int id = tid + j * 256;
            int row = id >> 3, cc = id & 7;
            cp16(bbase + row * ROWB + cc * 16,
                 &g_Wh[(size_t)(bn + row) * DIN + k0 + cc * 8]);
        }
    };
    auto ldsm_step = [&](uint32_t (&a)[4][4], uint32_t (&b)[4][4],
                         int slot, int s) {
        uint32_t ab = sbase + (uint32_t)slot * STAGE_BYTES + a_loff + (uint32_t)(s * 32);
        uint32_t bb = sbase + (uint32_t)slot * STAGE_BYTES + b_loff + (uint32_t)(s * 32);
#pragma unroll
        for (int mt = 0; mt < 4; mt++)
            ldsm4(a[mt][0], a[mt][1], a[mt][2], a[mt][3],
                  ab + (uint32_t)(mt * 16 * ROWB));
#pragma unroll
        for (int g = 0; g < 4; g++)
            ldsm4(b[g][0], b[g][1], b[g][2], b[g][3],
                  bb + (uint32_t)(g * 16 * ROWB));
    };
    auto mma_step = [&](uint32_t (&a)[4][4], uint32_t (&b)[4][4]) {
#pragma unroll
        for (int mt = 0; mt < 4; mt++)
#pragma unroll
            for (int g = 0; g < 4; g++) {
                mma16816(c[mt][2 * g],     a[mt], &b[g][0]);
                mma16816(c[mt][2 * g + 1], a[mt], &b[g][2]);
            }
    };

    // ---- prologue: fill 3 stages, land chunks 0..1, preload f0=(0,s0) ----
#pragma unroll
    for (int s = 0; s < STAGES; s++) {
        load_chunk(s, s);
        asm volatile("cp.async.commit_group;" ::: "memory");
    }
    asm volatile("cp.async.wait_group 1;" ::: "memory");
    __syncthreads();
    ldsm_step(a0, b0, 0, 0);

    // ---- mainloop: 64 iterations, one barrier each ----
    int slot_cur = 0, slot_nxt = 1;
    for (int i = 0; i < NCHUNK; i++) {
        ldsm_step(a1, b1, slot_cur, 1); mma_step(a0, b0);   // (i,s0)
        ldsm_step(a0, b0, slot_cur, 2); mma_step(a1, b1);   // (i,s1)
        ldsm_step(a1, b1, slot_cur, 3); mma_step(a0, b0);   // (i,s2)

        asm volatile("cp.async.wait_group 1;" ::: "memory"); // chunk i+1 landed
        __syncthreads();                                     // reads of chunk i done

        if (i + 1 < NCHUNK)
            ldsm_step(a0, b0, slot_nxt, 0);                  // (i+1,s0)
        if (i + STAGES < NCHUNK)
            load_chunk(i + STAGES, slot_cur);                // slot(i+3) == slot(i)
        asm volatile("cp.async.commit_group;" ::: "memory");

        mma_step(a1, b1);                                    // (i,s3)

        slot_cur = slot_nxt;
        slot_nxt = (slot_nxt == STAGES - 1) ? 0 : slot_nxt + 1;
    }

    // ---- epilogue: + bias, fp32 stores ----
    const int qrow = lane >> 2;
    const int qcol = (lane & 3) * 2;
#pragma unroll
    for (int mt = 0; mt < 4; mt++) {
        int r0 = bm + wm + mt * 16 + qrow;
#pragma unroll
        for (int g = 0; g < 4; g++) {
#pragma unroll
            for (int h = 0; h < 2; h++) {
                int col = bn + wn + g * 16 + h * 8 + qcol;
                float bb0 = sbias[col - bn];
                float bb1 = sbias[col - bn + 1];
                float* cc = c[mt][2 * g + h];
                *reinterpret_cast<float2*>(&out[(size_t)r0 * DOUT + col]) =
                    make_float2(cc[0] + bb0, cc[1] + bb1);
                *reinterpret_cast<float2*>(&out[(size_t)(r0 + 8) * DOUT + col]) =
                    make_float2(cc[2] + bb0, cc[3] + bb1);
            }
        }
    }
}

// ---------------------------------------------------------------------------
extern "C" void kernel_launch(void* const* d_in, const int* in_sizes, int n_in,
                              void* d_out, int out_size) {
    const float* x      = (const float*)d_in[0];
    const int*   qw     = (const int*)  d_in[1];
    const float* scales = (const float*)d_in[2];
    const float* bias   = (const float*)d_in[3];
    const float* lA     = (const float*)d_in[4];
    const float* lB     = (const float*)d_in[5];
    float*       out    = (float*)d_out;

    prep_kernel<<<W_BLOCKS + X_BLOCKS, 256>>>(qw, scales, lA, lB, x);
    {
        cudaFuncSetAttribute(qlora_hmma_kernel,
                             cudaFuncAttributeMaxDynamicSharedMemorySize, SMEM_DYN);
        dim3 grid(DOUT / BN, MROWS / BM);
        qlora_hmma_kernel<<<grid, 256, SMEM_DYN>>>(bias, out);
    }
}